// round 3
// baseline (speedup 1.0000x reference)
#include <cuda_runtime.h>
#include <math.h>

// ---------------------------------------------------------------------------
// EncoderLayer: RES=12000 residues, K=48 neighbors, H=128 hidden.
//
// Decomposition:
//   concat(h_i,h_j,e) @ W0  ==  h_i@W0a + h_j@W0b + e@W0c
//   and h_j@W0b == (node@W0b)[edge_idx]   (project-then-gather)
//
// Pipeline (all fp32, packed f32x2 FMA inner loops):
//   proj:  PA1 = node_h@W0a + b0 ; PB1 = node_h@W0b          (msg stage)
//   msg :  per residue: 3-layer MLP over 48 edges, k-sum, +node_h, LN1 -> NODE1
//   ff1 :  FFH = gelu(NODE1 @ ff_w0 + ff_b0)
//   ff2 :  node2 = LN2(NODE1 + FFH @ ff_w1 + ff_b1)  -> d_out (node section)
//   proj:  PA2 = node2@E0a + eb0 ; PB2 = node2@E0b            (edge stage)
//   edge:  per residue: 3-layer MLP over 48 edges, +edge_h, LNe -> d_out (edge)
// ---------------------------------------------------------------------------

#define RES   12000
#define KN    48
#define H     128
#define HH    (H*H)            // 16384 floats
#define TILE_FLOATS (KN*H)     // 6144 floats
#define NTHREADS 256

typedef unsigned long long u64;

// Scratch (no cudaMalloc allowed; __device__ globals are the sanctioned path)
__device__ float g_PA1[RES*H];
__device__ float g_PB1[RES*H];
__device__ float g_PA2[RES*H];
__device__ float g_PB2[RES*H];
__device__ float g_NODE1[RES*H];
__device__ float g_FFH[(size_t)RES*4*H];

// ---------------- packed f32x2 helpers (Blackwell sm_103a) -----------------
__device__ __forceinline__ u64 pk2(float x){
    u64 r; asm("mov.b64 %0, {%1, %1};" : "=l"(r) : "f"(x)); return r;
}
__device__ __forceinline__ u64 fma2(u64 a, u64 b, u64 c){
    u64 d; asm("fma.rn.f32x2 %0, %1, %2, %3;" : "=l"(d) : "l"(a), "l"(b), "l"(c)); return d;
}
__device__ __forceinline__ float2 up2(u64 v){
    float lo, hi; asm("mov.b64 {%0, %1}, %2;" : "=f"(lo), "=f"(hi) : "l"(v));
    return make_float2(lo, hi);
}
__device__ __forceinline__ float gelu(float x){
    // exact-erf GELU (reference uses approximate=False)
    return 0.5f * x * (1.0f + erff(x * 0.7071067811865475f));
}

// 48x128 += 48x128 @ 128x128, xs/ws in smem.
// thread (tx,ty): rows m = ty*6 .. ty*6+5 ; cols {2tx,2tx+1, 64+2tx,65+2tx}
// acc[2r] = pair (cols 2tx,2tx+1) of row r ; acc[2r+1] = pair (64+2tx,65+2tx)
__device__ __forceinline__ void mm48(const float* __restrict__ xs,
                                     const float* __restrict__ ws,
                                     int tx, int ty, u64 acc[12]){
    const float* xr = xs + ty*6*H;
    const u64* wa = (const u64*)(ws + 2*tx);
    const u64* wb = (const u64*)(ws + 64 + 2*tx);
    #pragma unroll 4
    for (int k = 0; k < H; k++){
        u64 w0 = wa[k*(H/2)];
        u64 w1 = wb[k*(H/2)];
        #pragma unroll
        for (int r = 0; r < 6; r++){
            u64 a = pk2(xr[r*H + k]);
            acc[2*r]   = fma2(a, w0, acc[2*r]);
            acc[2*r+1] = fma2(a, w1, acc[2*r+1]);
        }
    }
}

__device__ __forceinline__ void copy16k(float* dst, const float* src, int tid){
    const float4* s = (const float4*)src; float4* d = (float4*)dst;
    #pragma unroll 4
    for (int i = tid; i < HH/4; i += NTHREADS) d[i] = s[i];
}
__device__ __forceinline__ void copytile(float* dst, const float* src, int tid){
    const float4* s = (const float4*)src; float4* d = (float4*)dst;
    #pragma unroll
    for (int i = tid; i < TILE_FLOATS/4; i += NTHREADS) d[i] = s[i];
}

// ------------------------- proj: out = src@W (+bias) -----------------------
__global__ void __launch_bounds__(NTHREADS)
proj_kernel(const float* __restrict__ src, const float* __restrict__ w,
            const float* __restrict__ bias, int sel){
    extern __shared__ float sm[];
    float* ws = sm; float* xs = sm + HH;
    int tid = threadIdx.x, tx = tid & 31, ty = tid >> 5;
    copy16k(ws, w, tid);
    copytile(xs, src + (size_t)blockIdx.x*TILE_FLOATS, tid);
    __syncthreads();
    u64 acc[12];
    #pragma unroll
    for (int q = 0; q < 12; q++) acc[q] = 0ull;
    mm48(xs, ws, tx, ty, acc);
    float bv0=0.f, bv1=0.f, bv2=0.f, bv3=0.f;
    if (bias){ bv0=bias[2*tx]; bv1=bias[2*tx+1]; bv2=bias[64+2*tx]; bv3=bias[65+2*tx]; }
    float* outp = (sel==0) ? g_PA1 : (sel==1) ? g_PB1 : (sel==2) ? g_PA2 : g_PB2;
    int base = blockIdx.x * KN;
    #pragma unroll
    for (int r = 0; r < 6; r++){
        int m = ty*6 + r;
        float2 v0 = up2(acc[2*r]), v1 = up2(acc[2*r+1]);
        float* o = outp + (size_t)(base+m)*H;
        *(float2*)(o + 2*tx)      = make_float2(v0.x+bv0, v0.y+bv1);
        *(float2*)(o + 64 + 2*tx) = make_float2(v1.x+bv2, v1.y+bv3);
    }
}

// --------------------- message pass + k-sum + LN1 --------------------------
__global__ void __launch_bounds__(NTHREADS)
msg_kernel(const float* __restrict__ node_h, const float* __restrict__ edge_h,
           const float* __restrict__ w0c, const float* __restrict__ w1,
           const float* __restrict__ b1,  const float* __restrict__ w2,
           const float* __restrict__ b2,  const float* __restrict__ ln1_g,
           const float* __restrict__ ln1_b, const int* __restrict__ edge_idx){
    extern __shared__ float sm[];
    float* ws0 = sm; float* ws1 = sm + HH; float* ws2 = sm + 2*HH;
    float* xs  = sm + 3*HH;                       // TILE_FLOATS, also reduction scratch
    int tid = threadIdx.x, tx = tid & 31, ty = tid >> 5;

    copy16k(ws0, w0c, tid);
    copy16k(ws1, w1, tid);
    copy16k(ws2, w2, tid);
    float b1v0=b1[2*tx], b1v1=b1[2*tx+1], b1v2=b1[64+2*tx], b1v3=b1[65+2*tx];
    float lg=0.f, lb=0.f, b2t=0.f;
    if (tid < H){ lg=ln1_g[tid]; lb=ln1_b[tid]; b2t=b2[tid]; }
    __syncthreads();

    for (int i = blockIdx.x; i < RES; i += gridDim.x){
        copytile(xs, edge_h + (size_t)i*TILE_FLOATS, tid);
        int jr[6];
        #pragma unroll
        for (int r = 0; r < 6; r++) jr[r] = edge_idx[i*KN + ty*6 + r];
        __syncthreads();

        // layer 0: y0 = e@W0c + PA1[i] + PB1[j] ; x1 = gelu(y0)
        u64 acc[12];
        #pragma unroll
        for (int q = 0; q < 12; q++) acc[q] = 0ull;
        mm48(xs, ws0, tx, ty, acc);
        const float* pa = g_PA1 + (size_t)i*H;
        float pa0=pa[2*tx], pa1=pa[2*tx+1], pa2=pa[64+2*tx], pa3=pa[65+2*tx];
        __syncthreads();
        #pragma unroll
        for (int r = 0; r < 6; r++){
            const float* pb = g_PB1 + (size_t)jr[r]*H;
            float2 pb0 = *(const float2*)(pb + 2*tx);
            float2 pb1 = *(const float2*)(pb + 64 + 2*tx);
            float2 v0 = up2(acc[2*r]), v1 = up2(acc[2*r+1]);
            float* xr = xs + (ty*6+r)*H;
            *(float2*)(xr + 2*tx)      = make_float2(gelu(v0.x+pa0+pb0.x), gelu(v0.y+pa1+pb0.y));
            *(float2*)(xr + 64 + 2*tx) = make_float2(gelu(v1.x+pa2+pb1.x), gelu(v1.y+pa3+pb1.y));
        }
        __syncthreads();

        // layer 1: x2 = gelu(x1@W1 + b1)
        #pragma unroll
        for (int q = 0; q < 12; q++) acc[q] = 0ull;
        mm48(xs, ws1, tx, ty, acc);
        __syncthreads();
        #pragma unroll
        for (int r = 0; r < 6; r++){
            float2 v0 = up2(acc[2*r]), v1 = up2(acc[2*r+1]);
            float* xr = xs + (ty*6+r)*H;
            *(float2*)(xr + 2*tx)      = make_float2(gelu(v0.x+b1v0), gelu(v0.y+b1v1));
            *(float2*)(xr + 64 + 2*tx) = make_float2(gelu(v1.x+b1v2), gelu(v1.y+b1v3));
        }
        __syncthreads();

        // layer 2: y2 = x2@W2 (+b2 folded into the k-sum as 48*b2)
        #pragma unroll
        for (int q = 0; q < 12; q++) acc[q] = 0ull;
        mm48(xs, ws2, tx, ty, acc);
        float c0=0.f, c1=0.f, c2=0.f, c3=0.f;
        #pragma unroll
        for (int r = 0; r < 6; r++){
            float2 v0 = up2(acc[2*r]), v1 = up2(acc[2*r+1]);
            c0 += v0.x; c1 += v0.y; c2 += v1.x; c3 += v1.y;
        }
        __syncthreads();                       // xs reads done -> reuse as scratch
        *(float2*)(xs + ty*H + 2*tx)      = make_float2(c0, c1);
        *(float2*)(xs + ty*H + 64 + 2*tx) = make_float2(c2, c3);
        __syncthreads();
        float v = 0.f;
        if (tid < H){
            float s = 0.f;
            #pragma unroll
            for (int t = 0; t < 8; t++) s += xs[t*H + tid];
            v = node_h[(size_t)i*H + tid] + s + 48.0f*b2t;
            xs[1024 + tid] = v;
        }
        __syncthreads();
        if (tid < 32){
            float s = 0.f, q = 0.f;
            #pragma unroll
            for (int g = 0; g < 4; g++){ float t = xs[1024 + tid + 32*g]; s += t; q += t*t; }
            #pragma unroll
            for (int off = 16; off; off >>= 1){
                s += __shfl_xor_sync(0xffffffffu, s, off);
                q += __shfl_xor_sync(0xffffffffu, q, off);
            }
            if (tid == 0){
                float mean = s * (1.0f/H);
                float var  = q * (1.0f/H) - mean*mean;
                xs[1152] = mean;
                xs[1153] = rsqrtf(var + 1e-5f);
            }
        }
        __syncthreads();
        if (tid < H){
            g_NODE1[(size_t)i*H + tid] = (v - xs[1152]) * xs[1153] * lg + lb;
        }
        __syncthreads();                       // protect xs before next iteration
    }
}

// ----------------------- FF part 1: FFH = gelu(N1@W0+b0) -------------------
__global__ void __launch_bounds__(NTHREADS)
ff1_kernel(const float* __restrict__ w, const float* __restrict__ bias){
    extern __shared__ float sm[];
    float* ws = sm; float* xs = sm + HH;
    int tid = threadIdx.x, tx = tid & 31, ty = tid >> 5;
    int n0 = blockIdx.y * H;
    {   // strided copy: w is [128,512] row-major, take column block n0..n0+127
        float4* d = (float4*)ws;
        #pragma unroll 4
        for (int i = tid; i < HH/4; i += NTHREADS){
            int k = i >> 5, c = i & 31;
            d[i] = *(const float4*)(w + (size_t)k*(4*H) + n0 + 4*c);
        }
    }
    copytile(xs, g_NODE1 + (size_t)blockIdx.x*TILE_FLOATS, tid);
    __syncthreads();
    u64 acc[12];
    #pragma unroll
    for (int q = 0; q < 12; q++) acc[q] = 0ull;
    mm48(xs, ws, tx, ty, acc);
    float bv0=bias[n0+2*tx], bv1=bias[n0+2*tx+1], bv2=bias[n0+64+2*tx], bv3=bias[n0+65+2*tx];
    int base = blockIdx.x * KN;
    #pragma unroll
    for (int r = 0; r < 6; r++){
        int m = ty*6 + r;
        float2 v0 = up2(acc[2*r]), v1 = up2(acc[2*r+1]);
        float* o = g_FFH + (size_t)(base+m)*(4*H) + n0;
        *(float2*)(o + 2*tx)      = make_float2(gelu(v0.x+bv0), gelu(v0.y+bv1));
        *(float2*)(o + 64 + 2*tx) = make_float2(gelu(v1.x+bv2), gelu(v1.y+bv3));
    }
}

// ------------- FF part 2: node2 = LN2(N1 + FFH@W1 + b1) -> d_out -----------
__global__ void __launch_bounds__(NTHREADS)
ff2_kernel(const float* __restrict__ w, const float* __restrict__ bias,
           const float* __restrict__ ln2_g, const float* __restrict__ ln2_b,
           float* __restrict__ out_node){
    extern __shared__ float sm[];
    float* ws = sm; float* xs = sm + HH;
    int tid = threadIdx.x, tx = tid & 31, ty = tid >> 5;
    int base = blockIdx.x * KN;
    u64 acc[12];
    #pragma unroll
    for (int q = 0; q < 12; q++) acc[q] = 0ull;
    for (int c = 0; c < 4; c++){
        copy16k(ws, w + (size_t)c*H*H, tid);      // [512,128] rows c*128..c*128+127
        {
            float4* d = (float4*)xs;
            #pragma unroll
            for (int i = tid; i < TILE_FLOATS/4; i += NTHREADS){
                int m = i >> 5, cc = i & 31;
                d[i] = *(const float4*)(g_FFH + (size_t)(base+m)*(4*H) + c*H + 4*cc);
            }
        }
        __syncthreads();
        mm48(xs, ws, tx, ty, acc);
        __syncthreads();
    }
    float bv0=bias[2*tx], bv1=bias[2*tx+1], bv2=bias[64+2*tx], bv3=bias[65+2*tx];
    float lg0=ln2_g[2*tx], lg1=ln2_g[2*tx+1], lg2=ln2_g[64+2*tx], lg3=ln2_g[65+2*tx];
    float lb0=ln2_b[2*tx], lb1=ln2_b[2*tx+1], lb2=ln2_b[64+2*tx], lb3=ln2_b[65+2*tx];
    #pragma unroll
    for (int r = 0; r < 6; r++){
        int row = base + ty*6 + r;
        const float* n1 = g_NODE1 + (size_t)row*H;
        float2 a0 = *(const float2*)(n1 + 2*tx);
        float2 a1 = *(const float2*)(n1 + 64 + 2*tx);
        float2 v0 = up2(acc[2*r]), v1 = up2(acc[2*r+1]);
        float x0 = v0.x+bv0+a0.x, x1 = v0.y+bv1+a0.y;
        float x2 = v1.x+bv2+a1.x, x3 = v1.y+bv3+a1.y;
        float s = x0+x1+x2+x3, q = x0*x0+x1*x1+x2*x2+x3*x3;
        #pragma unroll
        for (int off = 16; off; off >>= 1){
            s += __shfl_xor_sync(0xffffffffu, s, off);
            q += __shfl_xor_sync(0xffffffffu, q, off);
        }
        float mean = s * (1.0f/H);
        float rstd = rsqrtf(q*(1.0f/H) - mean*mean + 1e-5f);
        float* o = out_node + (size_t)row*H;
        *(float2*)(o + 2*tx)      = make_float2((x0-mean)*rstd*lg0+lb0, (x1-mean)*rstd*lg1+lb1);
        *(float2*)(o + 64 + 2*tx) = make_float2((x2-mean)*rstd*lg2+lb2, (x3-mean)*rstd*lg3+lb3);
    }
}

// -------------------- edge update + LNe -> d_out (edge) --------------------
__global__ void __launch_bounds__(NTHREADS)
edge_kernel(const float* __restrict__ edge_h, const float* __restrict__ w0c,
            const float* __restrict__ w1, const float* __restrict__ b1,
            const float* __restrict__ w2, const float* __restrict__ b2,
            const float* __restrict__ lne_g, const float* __restrict__ lne_b,
            const int* __restrict__ edge_idx, float* __restrict__ out_edge){
    extern __shared__ float sm[];
    float* ws0 = sm; float* ws1 = sm + HH; float* ws2 = sm + 2*HH;
    float* xs  = sm + 3*HH;
    int tid = threadIdx.x, tx = tid & 31, ty = tid >> 5;

    copy16k(ws0, w0c, tid);
    copy16k(ws1, w1, tid);
    copy16k(ws2, w2, tid);
    float b1v0=b1[2*tx], b1v1=b1[2*tx+1], b1v2=b1[64+2*tx], b1v3=b1[65+2*tx];
    float b2v0=b2[2*tx], b2v1=b2[2*tx+1], b2v2=b2[64+2*tx], b2v3=b2[65+2*tx];
    float lg0=lne_g[2*tx], lg1=lne_g[2*tx+1], lg2=lne_g[64+2*tx], lg3=lne_g[65+2*tx];
    float lb0=lne_b[2*tx], lb1=lne_b[2*tx+1], lb2=lne_b[64+2*tx], lb3=lne_b[65+2*tx];
    __syncthreads();

    for (int i = blockIdx.x; i < RES; i += gridDim.x){
        copytile(xs, edge_h + (size_t)i*TILE_FLOATS, tid);
        int jr[6];
        #pragma unroll
        for (int r = 0; r < 6; r++) jr[r] = edge_idx[i*KN + ty*6 + r];
        __syncthreads();

        u64 acc[12];
        #pragma unroll
        for (int q = 0; q < 12; q++) acc[q] = 0ull;
        mm48(xs, ws0, tx, ty, acc);
        const float* pa = g_PA2 + (size_t)i*H;
        float pa0=pa[2*tx], pa1=pa[2*tx+1], pa2=pa[64+2*tx], pa3=pa[65+2*tx];
        __syncthreads();
        #pragma unroll
        for (int r = 0; r < 6; r++){
            const float* pb = g_PB2 + (size_t)jr[r]*H;
            float2 pb0 = *(const float2*)(pb + 2*tx);
            float2 pb1 = *(const float2*)(pb + 64 + 2*tx);
            float2 v0 = up2(acc[2*r]), v1 = up2(acc[2*r+1]);
            float* xr = xs + (ty*6+r)*H;
            *(float2*)(xr + 2*tx)      = make_float2(gelu(v0.x+pa0+pb0.x), gelu(v0.y+pa1+pb0.y));
            *(float2*)(xr + 64 + 2*tx) = make_float2(gelu(v1.x+pa2+pb1.x), gelu(v1.y+pa3+pb1.y));
        }
        __syncthreads();

        #pragma unroll
        for (int q = 0; q < 12; q++) acc[q] = 0ull;
        mm48(xs, ws1, tx, ty, acc);
        __syncthreads();
        #pragma unroll
        for (int r = 0; r < 6; r++){
            float2 v0 = up2(acc[2*r]), v1 = up2(acc[2*r+1]);
            float* xr = xs + (ty*6+r)*H;
            *(float2*)(xr + 2*tx)      = make_float2(gelu(v0.x+b1v0), gelu(v0.y+b1v1));
            *(float2*)(xr + 64 + 2*tx) = make_float2(gelu(v1.x+b1v2), gelu(v1.y+b1v3));
        }
        __syncthreads();

        #pragma unroll
        for (int q = 0; q < 12; q++) acc[q] = 0ull;
        mm48(xs, ws2, tx, ty, acc);
        __syncthreads();                        // xs free for next iteration

        #pragma unroll
        for (int r = 0; r < 6; r++){
            int m = ty*6 + r;
            const float* er = edge_h + ((size_t)i*KN + m)*H;
            float2 e0 = *(const float2*)(er + 2*tx);
            float2 e1 = *(const float2*)(er + 64 + 2*tx);
            float2 v0 = up2(acc[2*r]), v1 = up2(acc[2*r+1]);
            float x0 = e0.x+v0.x+b2v0, x1 = e0.y+v0.y+b2v1;
            float x2 = e1.x+v1.x+b2v2, x3 = e1.y+v1.y+b2v3;
            float s = x0+x1+x2+x3, q = x0*x0+x1*x1+x2*x2+x3*x3;
            #pragma unroll
            for (int off = 16; off; off >>= 1){
                s += __shfl_xor_sync(0xffffffffu, s, off);
                q += __shfl_xor_sync(0xffffffffu, q, off);
            }
            float mean = s * (1.0f/H);
            float rstd = rsqrtf(q*(1.0f/H) - mean*mean + 1e-5f);
            float* o = out_edge + ((size_t)i*KN + m)*H;
            *(float2*)(o + 2*tx)      = make_float2((x0-mean)*rstd*lg0+lb0, (x1-mean)*rstd*lg1+lb1);
            *(float2*)(o + 64 + 2*tx) = make_float2((x2-mean)*rstd*lg2+lb2, (x3-mean)*rstd*lg3+lb3);
        }
    }
}

// ---------------------------------------------------------------------------
extern "C" void kernel_launch(void* const* d_in, const int* in_sizes, int n_in,
                              void* d_out, int out_size){
    const float* node_h  = (const float*)d_in[0];
    const float* edge_h  = (const float*)d_in[1];
    const float* msg_w0  = (const float*)d_in[2];
    const float* msg_b0  = (const float*)d_in[3];
    const float* msg_w1  = (const float*)d_in[4];
    const float* msg_b1  = (const float*)d_in[5];
    const float* msg_w2  = (const float*)d_in[6];
    const float* msg_b2  = (const float*)d_in[7];
    const float* ff_w0   = (const float*)d_in[8];
    const float* ff_b0   = (const float*)d_in[9];
    const float* ff_w1   = (const float*)d_in[10];
    const float* ff_b1   = (const float*)d_in[11];
    const float* edge_w0 = (const float*)d_in[12];
    const float* edge_b0 = (const float*)d_in[13];
    const float* edge_w1 = (const float*)d_in[14];
    const float* edge_b1 = (const float*)d_in[15];
    const float* edge_w2 = (const float*)d_in[16];
    const float* edge_b2 = (const float*)d_in[17];
    const float* ln1_g   = (const float*)d_in[18];
    const float* ln1_b   = (const float*)d_in[19];
    const float* ln2_g   = (const float*)d_in[20];
    const float* ln2_b   = (const float*)d_in[21];
    const float* lne_g   = (const float*)d_in[22];
    const float* lne_b   = (const float*)d_in[23];
    const int*   edge_idx= (const int*)  d_in[24];

    float* out_node = (float*)d_out;                 // [12000,128]
    float* out_edge = out_node + (size_t)RES*H;      // [12000,48,128]

    const int SMEM_BIG   = (3*HH + TILE_FLOATS) * 4; // 221184 B
    const int SMEM_SMALL = (HH + TILE_FLOATS) * 4;   //  90112 B
    cudaFuncSetAttribute(proj_kernel, cudaFuncAttributeMaxDynamicSharedMemorySize, SMEM_SMALL);
    cudaFuncSetAttribute(ff1_kernel,  cudaFuncAttributeMaxDynamicSharedMemorySize, SMEM_SMALL);
    cudaFuncSetAttribute(ff2_kernel,  cudaFuncAttributeMaxDynamicSharedMemorySize, SMEM_SMALL);
    cudaFuncSetAttribute(msg_kernel,  cudaFuncAttributeMaxDynamicSharedMemorySize, SMEM_BIG);
    cudaFuncSetAttribute(edge_kernel, cudaFuncAttributeMaxDynamicSharedMemorySize, SMEM_BIG);

    int dev = 0, nsm = 148;
    if (cudaGetDevice(&dev) == cudaSuccess){
        int v = 0;
        if (cudaDeviceGetAttribute(&v, cudaDevAttrMultiProcessorCount, dev) == cudaSuccess && v > 0)
            nsm = v;
    }

    const int NBLK = RES / KN;   // 250, exact

    // message stage projections: PA1 = node@W0a + b0, PB1 = node@W0b
    proj_kernel<<<NBLK, NTHREADS, SMEM_SMALL>>>(node_h, msg_w0,           msg_b0, 0);
    proj_kernel<<<NBLK, NTHREADS, SMEM_SMALL>>>(node_h, msg_w0 + 128*H,   nullptr, 1);
    // fused message MLP + k-sum + LN1 -> NODE1
    msg_kernel<<<nsm, NTHREADS, SMEM_BIG>>>(node_h, edge_h, msg_w0 + 256*H,
                                            msg_w1, msg_b1, msg_w2, msg_b2,
                                            ln1_g, ln1_b, edge_idx);
    // feed-forward + LN2 -> node2 (d_out)
    ff1_kernel<<<dim3(NBLK, 4), NTHREADS, SMEM_SMALL>>>(ff_w0, ff_b0);
    ff2_kernel<<<NBLK, NTHREADS, SMEM_SMALL>>>(ff_w1, ff_b1, ln2_g, ln2_b, out_node);
    // edge stage projections from refreshed node states
    proj_kernel<<<NBLK, NTHREADS, SMEM_SMALL>>>(out_node, edge_w0,         edge_b0, 2);
    proj_kernel<<<NBLK, NTHREADS, SMEM_SMALL>>>(out_node, edge_w0 + 128*H, nullptr, 3);
    // fused edge MLP + residual + LNe -> d_out (edge section)
    edge_kernel<<<nsm, NTHREADS, SMEM_BIG>>>(edge_h, edge_w0 + 256*H,
                                             edge_w1, edge_b1, edge_w2, edge_b2,
                                             lne_g, lne_b, edge_idx, out_edge);
    (void)in_sizes; (void)n_in; (void)out_size;
}

// round 4
// speedup vs baseline: 1.0001x; 1.0001x over previous
#include <cuda_runtime.h>
#include <math.h>

// ---------------------------------------------------------------------------
// EncoderLayer: RES=12000 residues, K=48 neighbors, H=128 hidden.
//
// Decomposition:
//   concat(h_i,h_j,e) @ W0  ==  h_i@W0a + h_j@W0b + e@W0c
//   and h_j@W0b == (node@W0b)[edge_idx]   (project-then-gather)
//
// Pipeline (all fp32, packed f32x2 FMA inner loops):
//   proj:  PA1 = node_h@W0a + b0 ; PB1 = node_h@W0b          (msg stage)
//   msg :  per residue: 3-layer MLP over 48 edges, k-sum, +node_h, LN1 -> NODE1
//   ff1 :  FFH = gelu(NODE1 @ ff_w0 + ff_b0)
//   ff2 :  node2 = LN2(NODE1 + FFH @ ff_w1 + ff_b1)  -> d_out (node section)
//   proj:  PA2 = node2@E0a + eb0 ; PB2 = node2@E0b            (edge stage)
//   edge:  per residue: 3-layer MLP over 48 edges, +edge_h, LNe -> d_out (edge)
// ---------------------------------------------------------------------------

#define RES   12000
#define KN    48
#define H     128
#define HH    (H*H)            // 16384 floats
#define TILE_FLOATS (KN*H)     // 6144 floats
#define NTHREADS 256

typedef unsigned long long u64;

// Scratch (no cudaMalloc allowed; __device__ globals are the sanctioned path)
__device__ float g_PA1[RES*H];
__device__ float g_PB1[RES*H];
__device__ float g_PA2[RES*H];
__device__ float g_PB2[RES*H];
__device__ float g_NODE1[RES*H];
__device__ float g_FFH[(size_t)RES*4*H];

// ---------------- packed f32x2 helpers (Blackwell sm_103a) -----------------
__device__ __forceinline__ u64 pk2(float x){
    u64 r; asm("mov.b64 %0, {%1, %1};" : "=l"(r) : "f"(x)); return r;
}
__device__ __forceinline__ u64 fma2(u64 a, u64 b, u64 c){
    u64 d; asm("fma.rn.f32x2 %0, %1, %2, %3;" : "=l"(d) : "l"(a), "l"(b), "l"(c)); return d;
}
__device__ __forceinline__ float2 up2(u64 v){
    float lo, hi; asm("mov.b64 {%0, %1}, %2;" : "=f"(lo), "=f"(hi) : "l"(v));
    return make_float2(lo, hi);
}
__device__ __forceinline__ float gelu(float x){
    // exact-erf GELU (reference uses approximate=False)
    return 0.5f * x * (1.0f + erff(x * 0.7071067811865475f));
}

// 48x128 += 48x128 @ 128x128, xs/ws in smem.
// thread (tx,ty): rows m = ty*6 .. ty*6+5 ; cols {2tx,2tx+1, 64+2tx,65+2tx}
// acc[2r] = pair (cols 2tx,2tx+1) of row r ; acc[2r+1] = pair (64+2tx,65+2tx)
__device__ __forceinline__ void mm48(const float* __restrict__ xs,
                                     const float* __restrict__ ws,
                                     int tx, int ty, u64 acc[12]){
    const float* xr = xs + ty*6*H;
    const u64* wa = (const u64*)(ws + 2*tx);
    const u64* wb = (const u64*)(ws + 64 + 2*tx);
    #pragma unroll 4
    for (int k = 0; k < H; k++){
        u64 w0 = wa[k*(H/2)];
        u64 w1 = wb[k*(H/2)];
        #pragma unroll
        for (int r = 0; r < 6; r++){
            u64 a = pk2(xr[r*H + k]);
            acc[2*r]   = fma2(a, w0, acc[2*r]);
            acc[2*r+1] = fma2(a, w1, acc[2*r+1]);
        }
    }
}

__device__ __forceinline__ void copy16k(float* dst, const float* src, int tid){
    const float4* s = (const float4*)src; float4* d = (float4*)dst;
    #pragma unroll 4
    for (int i = tid; i < HH/4; i += NTHREADS) d[i] = s[i];
}
__device__ __forceinline__ void copytile(float* dst, const float* src, int tid){
    const float4* s = (const float4*)src; float4* d = (float4*)dst;
    #pragma unroll
    for (int i = tid; i < TILE_FLOATS/4; i += NTHREADS) d[i] = s[i];
}

// ------------------------- proj: out = src@W (+bias) -----------------------
__global__ void __launch_bounds__(NTHREADS)
proj_kernel(const float* __restrict__ src, const float* __restrict__ w,
            const float* __restrict__ bias, int sel){
    extern __shared__ float sm[];
    float* ws = sm; float* xs = sm + HH;
    int tid = threadIdx.x, tx = tid & 31, ty = tid >> 5;
    copy16k(ws, w, tid);
    copytile(xs, src + (size_t)blockIdx.x*TILE_FLOATS, tid);
    __syncthreads();
    u64 acc[12];
    #pragma unroll
    for (int q = 0; q < 12; q++) acc[q] = 0ull;
    mm48(xs, ws, tx, ty, acc);
    float bv0=0.f, bv1=0.f, bv2=0.f, bv3=0.f;
    if (bias){ bv0=bias[2*tx]; bv1=bias[2*tx+1]; bv2=bias[64+2*tx]; bv3=bias[65+2*tx]; }
    float* outp = (sel==0) ? g_PA1 : (sel==1) ? g_PB1 : (sel==2) ? g_PA2 : g_PB2;
    int base = blockIdx.x * KN;
    #pragma unroll
    for (int r = 0; r < 6; r++){
        int m = ty*6 + r;
        float2 v0 = up2(acc[2*r]), v1 = up2(acc[2*r+1]);
        float* o = outp + (size_t)(base+m)*H;
        *(float2*)(o + 2*tx)      = make_float2(v0.x+bv0, v0.y+bv1);
        *(float2*)(o + 64 + 2*tx) = make_float2(v1.x+bv2, v1.y+bv3);
    }
}

// --------------------- message pass + k-sum + LN1 --------------------------
__global__ void __launch_bounds__(NTHREADS)
msg_kernel(const float* __restrict__ node_h, const float* __restrict__ edge_h,
           const float* __restrict__ w0c, const float* __restrict__ w1,
           const float* __restrict__ b1,  const float* __restrict__ w2,
           const float* __restrict__ b2,  const float* __restrict__ ln1_g,
           const float* __restrict__ ln1_b, const int* __restrict__ edge_idx){
    extern __shared__ float sm[];
    float* ws0 = sm; float* ws1 = sm + HH; float* ws2 = sm + 2*HH;
    float* xs  = sm + 3*HH;                       // TILE_FLOATS, also reduction scratch
    int tid = threadIdx.x, tx = tid & 31, ty = tid >> 5;

    copy16k(ws0, w0c, tid);
    copy16k(ws1, w1, tid);
    copy16k(ws2, w2, tid);
    float b1v0=b1[2*tx], b1v1=b1[2*tx+1], b1v2=b1[64+2*tx], b1v3=b1[65+2*tx];
    float lg=0.f, lb=0.f, b2t=0.f;
    if (tid < H){ lg=ln1_g[tid]; lb=ln1_b[tid]; b2t=b2[tid]; }
    __syncthreads();

    for (int i = blockIdx.x; i < RES; i += gridDim.x){
        copytile(xs, edge_h + (size_t)i*TILE_FLOATS, tid);
        int jr[6];
        #pragma unroll
        for (int r = 0; r < 6; r++) jr[r] = edge_idx[i*KN + ty*6 + r];
        __syncthreads();

        // layer 0: y0 = e@W0c + PA1[i] + PB1[j] ; x1 = gelu(y0)
        u64 acc[12];
        #pragma unroll
        for (int q = 0; q < 12; q++) acc[q] = 0ull;
        mm48(xs, ws0, tx, ty, acc);
        const float* pa = g_PA1 + (size_t)i*H;
        float pa0=pa[2*tx], pa1=pa[2*tx+1], pa2=pa[64+2*tx], pa3=pa[65+2*tx];
        __syncthreads();
        #pragma unroll
        for (int r = 0; r < 6; r++){
            const float* pb = g_PB1 + (size_t)jr[r]*H;
            float2 pb0 = *(const float2*)(pb + 2*tx);
            float2 pb1 = *(const float2*)(pb + 64 + 2*tx);
            float2 v0 = up2(acc[2*r]), v1 = up2(acc[2*r+1]);
            float* xr = xs + (ty*6+r)*H;
            *(float2*)(xr + 2*tx)      = make_float2(gelu(v0.x+pa0+pb0.x), gelu(v0.y+pa1+pb0.y));
            *(float2*)(xr + 64 + 2*tx) = make_float2(gelu(v1.x+pa2+pb1.x), gelu(v1.y+pa3+pb1.y));
        }
        __syncthreads();

        // layer 1: x2 = gelu(x1@W1 + b1)
        #pragma unroll
        for (int q = 0; q < 12; q++) acc[q] = 0ull;
        mm48(xs, ws1, tx, ty, acc);
        __syncthreads();
        #pragma unroll
        for (int r = 0; r < 6; r++){
            float2 v0 = up2(acc[2*r]), v1 = up2(acc[2*r+1]);
            float* xr = xs + (ty*6+r)*H;
            *(float2*)(xr + 2*tx)      = make_float2(gelu(v0.x+b1v0), gelu(v0.y+b1v1));
            *(float2*)(xr + 64 + 2*tx) = make_float2(gelu(v1.x+b1v2), gelu(v1.y+b1v3));
        }
        __syncthreads();

        // layer 2: y2 = x2@W2 (+b2 folded into the k-sum as 48*b2)
        #pragma unroll
        for (int q = 0; q < 12; q++) acc[q] = 0ull;
        mm48(xs, ws2, tx, ty, acc);
        float c0=0.f, c1=0.f, c2=0.f, c3=0.f;
        #pragma unroll
        for (int r = 0; r < 6; r++){
            float2 v0 = up2(acc[2*r]), v1 = up2(acc[2*r+1]);
            c0 += v0.x; c1 += v0.y; c2 += v1.x; c3 += v1.y;
        }
        __syncthreads();                       // xs reads done -> reuse as scratch
        *(float2*)(xs + ty*H + 2*tx)      = make_float2(c0, c1);
        *(float2*)(xs + ty*H + 64 + 2*tx) = make_float2(c2, c3);
        __syncthreads();
        float v = 0.f;
        if (tid < H){
            float s = 0.f;
            #pragma unroll
            for (int t = 0; t < 8; t++) s += xs[t*H + tid];
            v = node_h[(size_t)i*H + tid] + s + 48.0f*b2t;
            xs[1024 + tid] = v;
        }
        __syncthreads();
        if (tid < 32){
            float s = 0.f, q = 0.f;
            #pragma unroll
            for (int g = 0; g < 4; g++){ float t = xs[1024 + tid + 32*g]; s += t; q += t*t; }
            #pragma unroll
            for (int off = 16; off; off >>= 1){
                s += __shfl_xor_sync(0xffffffffu, s, off);
                q += __shfl_xor_sync(0xffffffffu, q, off);
            }
            if (tid == 0){
                float mean = s * (1.0f/H);
                float var  = q * (1.0f/H) - mean*mean;
                xs[1152] = mean;
                xs[1153] = rsqrtf(var + 1e-5f);
            }
        }
        __syncthreads();
        if (tid < H){
            g_NODE1[(size_t)i*H + tid] = (v - xs[1152]) * xs[1153] * lg + lb;
        }
        __syncthreads();                       // protect xs before next iteration
    }
}

// ----------------------- FF part 1: FFH = gelu(N1@W0+b0) -------------------
__global__ void __launch_bounds__(NTHREADS)
ff1_kernel(const float* __restrict__ w, const float* __restrict__ bias){
    extern __shared__ float sm[];
    float* ws = sm; float* xs = sm + HH;
    int tid = threadIdx.x, tx = tid & 31, ty = tid >> 5;
    int n0 = blockIdx.y * H;
    {   // strided copy: w is [128,512] row-major, take column block n0..n0+127
        float4* d = (float4*)ws;
        #pragma unroll 4
        for (int i = tid; i < HH/4; i += NTHREADS){
            int k = i >> 5, c = i & 31;
            d[i] = *(const float4*)(w + (size_t)k*(4*H) + n0 + 4*c);
        }
    }
    copytile(xs, g_NODE1 + (size_t)blockIdx.x*TILE_FLOATS, tid);
    __syncthreads();
    u64 acc[12];
    #pragma unroll
    for (int q = 0; q < 12; q++) acc[q] = 0ull;
    mm48(xs, ws, tx, ty, acc);
    float bv0=bias[n0+2*tx], bv1=bias[n0+2*tx+1], bv2=bias[n0+64+2*tx], bv3=bias[n0+65+2*tx];
    int base = blockIdx.x * KN;
    #pragma unroll
    for (int r = 0; r < 6; r++){
        int m = ty*6 + r;
        float2 v0 = up2(acc[2*r]), v1 = up2(acc[2*r+1]);
        float* o = g_FFH + (size_t)(base+m)*(4*H) + n0;
        *(float2*)(o + 2*tx)      = make_float2(gelu(v0.x+bv0), gelu(v0.y+bv1));
        *(float2*)(o + 64 + 2*tx) = make_float2(gelu(v1.x+bv2), gelu(v1.y+bv3));
    }
}

// ------------- FF part 2: node2 = LN2(N1 + FFH@W1 + b1) -> d_out -----------
__global__ void __launch_bounds__(NTHREADS)
ff2_kernel(const float* __restrict__ w, const float* __restrict__ bias,
           const float* __restrict__ ln2_g, const float* __restrict__ ln2_b,
           float* __restrict__ out_node){
    extern __shared__ float sm[];
    float* ws = sm; float* xs = sm + HH;
    int tid = threadIdx.x, tx = tid & 31, ty = tid >> 5;
    int base = blockIdx.x * KN;
    u64 acc[12];
    #pragma unroll
    for (int q = 0; q < 12; q++) acc[q] = 0ull;
    for (int c = 0; c < 4; c++){
        copy16k(ws, w + (size_t)c*H*H, tid);      // [512,128] rows c*128..c*128+127
        {
            float4* d = (float4*)xs;
            #pragma unroll
            for (int i = tid; i < TILE_FLOATS/4; i += NTHREADS){
                int m = i >> 5, cc = i & 31;
                d[i] = *(const float4*)(g_FFH + (size_t)(base+m)*(4*H) + c*H + 4*cc);
            }
        }
        __syncthreads();
        mm48(xs, ws, tx, ty, acc);
        __syncthreads();
    }
    float bv0=bias[2*tx], bv1=bias[2*tx+1], bv2=bias[64+2*tx], bv3=bias[65+2*tx];
    float lg0=ln2_g[2*tx], lg1=ln2_g[2*tx+1], lg2=ln2_g[64+2*tx], lg3=ln2_g[65+2*tx];
    float lb0=ln2_b[2*tx], lb1=ln2_b[2*tx+1], lb2=ln2_b[64+2*tx], lb3=ln2_b[65+2*tx];
    #pragma unroll
    for (int r = 0; r < 6; r++){
        int row = base + ty*6 + r;
        const float* n1 = g_NODE1 + (size_t)row*H;
        float2 a0 = *(const float2*)(n1 + 2*tx);
        float2 a1 = *(const float2*)(n1 + 64 + 2*tx);
        float2 v0 = up2(acc[2*r]), v1 = up2(acc[2*r+1]);
        float x0 = v0.x+bv0+a0.x, x1 = v0.y+bv1+a0.y;
        float x2 = v1.x+bv2+a1.x, x3 = v1.y+bv3+a1.y;
        float s = x0+x1+x2+x3, q = x0*x0+x1*x1+x2*x2+x3*x3;
        #pragma unroll
        for (int off = 16; off; off >>= 1){
            s += __shfl_xor_sync(0xffffffffu, s, off);
            q += __shfl_xor_sync(0xffffffffu, q, off);
        }
        float mean = s * (1.0f/H);
        float rstd = rsqrtf(q*(1.0f/H) - mean*mean + 1e-5f);
        float* o = out_node + (size_t)row*H;
        *(float2*)(o + 2*tx)      = make_float2((x0-mean)*rstd*lg0+lb0, (x1-mean)*rstd*lg1+lb1);
        *(float2*)(o + 64 + 2*tx) = make_float2((x2-mean)*rstd*lg2+lb2, (x3-mean)*rstd*lg3+lb3);
    }
}

// -------------------- edge update + LNe -> d_out (edge) --------------------
__global__ void __launch_bounds__(NTHREADS)
edge_kernel(const float* __restrict__ edge_h, const float* __restrict__ w0c,
            const float* __restrict__ w1, const float* __restrict__ b1,
            const float* __restrict__ w2, const float* __restrict__ b2,
            const float* __restrict__ lne_g, const float* __restrict__ lne_b,
            const int* __restrict__ edge_idx, float* __restrict__ out_edge){
    extern __shared__ float sm[];
    float* ws0 = sm; float* ws1 = sm + HH; float* ws2 = sm + 2*HH;
    float* xs  = sm + 3*HH;
    int tid = threadIdx.x, tx = tid & 31, ty = tid >> 5;

    copy16k(ws0, w0c, tid);
    copy16k(ws1, w1, tid);
    copy16k(ws2, w2, tid);
    float b1v0=b1[2*tx], b1v1=b1[2*tx+1], b1v2=b1[64+2*tx], b1v3=b1[65+2*tx];
    float b2v0=b2[2*tx], b2v1=b2[2*tx+1], b2v2=b2[64+2*tx], b2v3=b2[65+2*tx];
    float lg0=lne_g[2*tx], lg1=lne_g[2*tx+1], lg2=lne_g[64+2*tx], lg3=lne_g[65+2*tx];
    float lb0=lne_b[2*tx], lb1=lne_b[2*tx+1], lb2=lne_b[64+2*tx], lb3=lne_b[65+2*tx];
    __syncthreads();

    for (int i = blockIdx.x; i < RES; i += gridDim.x){
        copytile(xs, edge_h + (size_t)i*TILE_FLOATS, tid);
        int jr[6];
        #pragma unroll
        for (int r = 0; r < 6; r++) jr[r] = edge_idx[i*KN + ty*6 + r];
        __syncthreads();

        u64 acc[12];
        #pragma unroll
        for (int q = 0; q < 12; q++) acc[q] = 0ull;
        mm48(xs, ws0, tx, ty, acc);
        const float* pa = g_PA2 + (size_t)i*H;
        float pa0=pa[2*tx], pa1=pa[2*tx+1], pa2=pa[64+2*tx], pa3=pa[65+2*tx];
        __syncthreads();
        #pragma unroll
        for (int r = 0; r < 6; r++){
            const float* pb = g_PB2 + (size_t)jr[r]*H;
            float2 pb0 = *(const float2*)(pb + 2*tx);
            float2 pb1 = *(const float2*)(pb + 64 + 2*tx);
            float2 v0 = up2(acc[2*r]), v1 = up2(acc[2*r+1]);
            float* xr = xs + (ty*6+r)*H;
            *(float2*)(xr + 2*tx)      = make_float2(gelu(v0.x+pa0+pb0.x), gelu(v0.y+pa1+pb0.y));
            *(float2*)(xr + 64 + 2*tx) = make_float2(gelu(v1.x+pa2+pb1.x), gelu(v1.y+pa3+pb1.y));
        }
        __syncthreads();

        #pragma unroll
        for (int q = 0; q < 12; q++) acc[q] = 0ull;
        mm48(xs, ws1, tx, ty, acc);
        __syncthreads();
        #pragma unroll
        for (int r = 0; r < 6; r++){
            float2 v0 = up2(acc[2*r]), v1 = up2(acc[2*r+1]);
            float* xr = xs + (ty*6+r)*H;
            *(float2*)(xr + 2*tx)      = make_float2(gelu(v0.x+b1v0), gelu(v0.y+b1v1));
            *(float2*)(xr + 64 + 2*tx) = make_float2(gelu(v1.x+b1v2), gelu(v1.y+b1v3));
        }
        __syncthreads();

        #pragma unroll
        for (int q = 0; q < 12; q++) acc[q] = 0ull;
        mm48(xs, ws2, tx, ty, acc);
        __syncthreads();                        // xs free for next iteration

        #pragma unroll
        for (int r = 0; r < 6; r++){
            int m = ty*6 + r;
            const float* er = edge_h + ((size_t)i*KN + m)*H;
            float2 e0 = *(const float2*)(er + 2*tx);
            float2 e1 = *(const float2*)(er + 64 + 2*tx);
            float2 v0 = up2(acc[2*r]), v1 = up2(acc[2*r+1]);
            float x0 = e0.x+v0.x+b2v0, x1 = e0.y+v0.y+b2v1;
            float x2 = e1.x+v1.x+b2v2, x3 = e1.y+v1.y+b2v3;
            float s = x0+x1+x2+x3, q = x0*x0+x1*x1+x2*x2+x3*x3;
            #pragma unroll
            for (int off = 16; off; off >>= 1){
                s += __shfl_xor_sync(0xffffffffu, s, off);
                q += __shfl_xor_sync(0xffffffffu, q, off);
            }
            float mean = s * (1.0f/H);
            float rstd = rsqrtf(q*(1.0f/H) - mean*mean + 1e-5f);
            float* o = out_edge + ((size_t)i*KN + m)*H;
            *(float2*)(o + 2*tx)      = make_float2((x0-mean)*rstd*lg0+lb0, (x1-mean)*rstd*lg1+lb1);
            *(float2*)(o + 64 + 2*tx) = make_float2((x2-mean)*rstd*lg2+lb2, (x3-mean)*rstd*lg3+lb3);
        }
    }
}

// ---------------------------------------------------------------------------
extern "C" void kernel_launch(void* const* d_in, const int* in_sizes, int n_in,
                              void* d_out, int out_size){
    const float* node_h  = (const float*)d_in[0];
    const float* edge_h  = (const float*)d_in[1];
    const float* msg_w0  = (const float*)d_in[2];
    const float* msg_b0  = (const float*)d_in[3];
    const float* msg_w1  = (const float*)d_in[4];
    const float* msg_b1  = (const float*)d_in[5];
    const float* msg_w2  = (const float*)d_in[6];
    const float* msg_b2  = (const float*)d_in[7];
    const float* ff_w0   = (const float*)d_in[8];
    const float* ff_b0   = (const float*)d_in[9];
    const float* ff_w1   = (const float*)d_in[10];
    const float* ff_b1   = (const float*)d_in[11];
    const float* edge_w0 = (const float*)d_in[12];
    const float* edge_b0 = (const float*)d_in[13];
    const float* edge_w1 = (const float*)d_in[14];
    const float* edge_b1 = (const float*)d_in[15];
    const float* edge_w2 = (const float*)d_in[16];
    const float* edge_b2 = (const float*)d_in[17];
    const float* ln1_g   = (const float*)d_in[18];
    const float* ln1_b   = (const float*)d_in[19];
    const float* ln2_g   = (const float*)d_in[20];
    const float* ln2_b   = (const float*)d_in[21];
    const float* lne_g   = (const float*)d_in[22];
    const float* lne_b   = (const float*)d_in[23];
    const int*   edge_idx= (const int*)  d_in[24];

    float* out_node = (float*)d_out;                 // [12000,128]
    float* out_edge = out_node + (size_t)RES*H;      // [12000,48,128]

    const int SMEM_BIG   = (3*HH + TILE_FLOATS) * 4; // 221184 B
    const int SMEM_SMALL = (HH + TILE_FLOATS) * 4;   //  90112 B
    cudaFuncSetAttribute(proj_kernel, cudaFuncAttributeMaxDynamicSharedMemorySize, SMEM_SMALL);
    cudaFuncSetAttribute(ff1_kernel,  cudaFuncAttributeMaxDynamicSharedMemorySize, SMEM_SMALL);
    cudaFuncSetAttribute(ff2_kernel,  cudaFuncAttributeMaxDynamicSharedMemorySize, SMEM_SMALL);
    cudaFuncSetAttribute(msg_kernel,  cudaFuncAttributeMaxDynamicSharedMemorySize, SMEM_BIG);
    cudaFuncSetAttribute(edge_kernel, cudaFuncAttributeMaxDynamicSharedMemorySize, SMEM_BIG);

    int dev = 0, nsm = 148;
    if (cudaGetDevice(&dev) == cudaSuccess){
        int v = 0;
        if (cudaDeviceGetAttribute(&v, cudaDevAttrMultiProcessorCount, dev) == cudaSuccess && v > 0)
            nsm = v;
    }

    const int NBLK = RES / KN;   // 250, exact

    // message stage projections: PA1 = node@W0a + b0, PB1 = node@W0b
    proj_kernel<<<NBLK, NTHREADS, SMEM_SMALL>>>(node_h, msg_w0,           msg_b0, 0);
    proj_kernel<<<NBLK, NTHREADS, SMEM_SMALL>>>(node_h, msg_w0 + 128*H,   nullptr, 1);
    // fused message MLP + k-sum + LN1 -> NODE1
    msg_kernel<<<nsm, NTHREADS, SMEM_BIG>>>(node_h, edge_h, msg_w0 + 256*H,
                                            msg_w1, msg_b1, msg_w2, msg_b2,
                                            ln1_g, ln1_b, edge_idx);
    // feed-forward + LN2 -> node2 (d_out)
    ff1_kernel<<<dim3(NBLK, 4), NTHREADS, SMEM_SMALL>>>(ff_w0, ff_b0);
    ff2_kernel<<<NBLK, NTHREADS, SMEM_SMALL>>>(ff_w1, ff_b1, ln2_g, ln2_b, out_node);
    // edge stage projections from refreshed node states
    proj_kernel<<<NBLK, NTHREADS, SMEM_SMALL>>>(out_node, edge_w0,         edge_b0, 2);
    proj_kernel<<<NBLK, NTHREADS, SMEM_SMALL>>>(out_node, edge_w0 + 128*H, nullptr, 3);
    // fused edge MLP + residual + LNe -> d_out (edge section)
    edge_kernel<<<nsm, NTHREADS, SMEM_BIG>>>(edge_h, edge_w0 + 256*H,
                                             edge_w1, edge_b1, edge_w2, edge_b2,
                                             lne_g, lne_b, edge_idx, out_edge);
    (void)in_sizes; (void)n_in; (void)out_size;
}